// round 1
// baseline (speedup 1.0000x reference)
#include <cuda_runtime.h>

#define T_STEPS 20
#define BATCH   262144
#define BETAF   0.9f
#define THRESHF 1.0f

using u64 = unsigned long long;

__device__ __forceinline__ u64 pack2(float lo, float hi) {
    u64 r; asm("mov.b64 %0, {%1, %2};" : "=l"(r) : "f"(lo), "f"(hi)); return r;
}
__device__ __forceinline__ void unpack2(u64 v, float &lo, float &hi) {
    asm("mov.b64 {%0, %1}, %2;" : "=f"(lo), "=f"(hi) : "l"(v));
}
// Packed dual fp32 FMA (sm_103a): 2 MACs per instruction on the fma pipe.
__device__ __forceinline__ u64 ffma2(u64 a, u64 b, u64 c) {
    u64 d; asm("fma.rn.f32x2 %0, %1, %2, %3;" : "=l"(d) : "l"(a), "l"(b), "l"(c)); return d;
}

// Dot product of a binary spike vector (bitmask) against pair-packed weights.
// w row stride = 2*PAIRS (total output pairs of the layer), this thread covers PAIRS pairs.
template<typename MT, int NIN, int PAIRS>
__device__ __forceinline__ void dot_mask(MT hbits, const u64* __restrict__ w, u64* acc) {
#pragma unroll
    for (int k = 0; k < PAIRS; ++k) acc[k] = 0ull;
#pragma unroll
    for (int i = 0; i < NIN; ++i) {
        float hv = ((hbits >> i) & (MT)1) ? 1.0f : 0.0f;
        u64 h2 = pack2(hv, hv);
#pragma unroll
        for (int k = 0; k < PAIRS; ++k)
            acc[k] = ffma2(h2, w[i * (2 * PAIRS) + k], acc[k]);
    }
}

// LIF update (reset_mechanism='subtract', reset based on incoming mem),
// returns spike bitmask over this thread's 2*PAIRS neurons.
template<int PAIRS>
__device__ __forceinline__ unsigned lif_update(const u64* acc, float* mem) {
    unsigned msk = 0;
#pragma unroll
    for (int k = 0; k < PAIRS; ++k) {
        float a0, a1; unpack2(acc[k], a0, a1);
        float mA = mem[2 * k], mB = mem[2 * k + 1];
        float rA = mA > THRESHF ? THRESHF : 0.0f;
        float rB = mB > THRESHF ? THRESHF : 0.0f;
        mA = fmaf(BETAF, mA, a0 - rA);
        mB = fmaf(BETAF, mB, a1 - rB);
        mem[2 * k] = mA; mem[2 * k + 1] = mB;
        if (mA > THRESHF) msk |= 1u << (2 * k);
        if (mB > THRESHF) msk |= 1u << (2 * k + 1);
    }
    return msk;
}

__global__ __launch_bounds__(256) void lif_kernel(
    const float* __restrict__ x,
    const float* __restrict__ W1, const float* __restrict__ W2,
    const float* __restrict__ W3, const float* __restrict__ W4,
    const float* __restrict__ W5, float* __restrict__ out)
{
    // Pair-packed weights in shared: sW[l][i][j2] = (W[2*j2][i], W[2*j2+1][i])
    __shared__ u64 sW1[10 * 32];
    __shared__ u64 sW2[64 * 16];
    __shared__ u64 sW3[32 * 16];
    __shared__ u64 sW4[32 * 8];
    __shared__ u64 sW5[16 * 4];   // layer 5 padded 6 -> 8 outputs (rows 6,7 = 0)

    for (int idx = threadIdx.x; idx < 10 * 32; idx += 256) {
        int i = idx >> 5, j = idx & 31;
        sW1[idx] = pack2(W1[(2 * j) * 10 + i], W1[(2 * j + 1) * 10 + i]);
    }
    for (int idx = threadIdx.x; idx < 64 * 16; idx += 256) {
        int i = idx >> 4, j = idx & 15;
        sW2[idx] = pack2(W2[(2 * j) * 64 + i], W2[(2 * j + 1) * 64 + i]);
    }
    for (int idx = threadIdx.x; idx < 32 * 16; idx += 256) {
        int i = idx >> 4, j = idx & 15;
        sW3[idx] = pack2(W3[(2 * j) * 32 + i], W3[(2 * j + 1) * 32 + i]);
    }
    for (int idx = threadIdx.x; idx < 32 * 8; idx += 256) {
        int i = idx >> 3, j = idx & 7;
        sW4[idx] = pack2(W4[(2 * j) * 32 + i], W4[(2 * j + 1) * 32 + i]);
    }
    for (int idx = threadIdx.x; idx < 16 * 4; idx += 256) {
        int i = idx >> 2, j = idx & 3;
        int r0 = 2 * j, r1 = 2 * j + 1;
        float a = (r0 < 6) ? W5[r0 * 16 + i] : 0.0f;
        float b = (r1 < 6) ? W5[r1 * 16 + i] : 0.0f;
        sW5[idx] = pack2(a, b);
    }
    __syncthreads();

    int gtid = blockIdx.x * 256 + threadIdx.x;
    int e    = gtid >> 1;   // batch element
    int half = gtid & 1;    // which half of each layer's neurons this thread owns

    // Membrane state (registers). Per-thread: half of each layer.
    float m1[32], m2[16], m3[16], m4[8], m5[4];
#pragma unroll
    for (int k = 0; k < 32; ++k) m1[k] = 0.0f;
#pragma unroll
    for (int k = 0; k < 16; ++k) { m2[k] = 0.0f; m3[k] = 0.0f; }
#pragma unroll
    for (int k = 0; k < 8; ++k) m4[k] = 0.0f;
#pragma unroll
    for (int k = 0; k < 4; ++k) m5[k] = 0.0f;

    const u64* w1 = sW1 + half * 16;
    const u64* w2 = sW2 + half * 8;
    const u64* w3 = sW3 + half * 8;
    const u64* w4 = sW4 + half * 4;
    const u64* w5 = sW5 + half * 2;

    for (int t = 0; t < T_STEPS; ++t) {
        // ---- load x[t, e, 0:10] (8B-aligned: 10 floats = 40B stride) ----
        const float2* xp = (const float2*)(x + ((size_t)t * BATCH + (size_t)e) * 10);
        float xv[10];
#pragma unroll
        for (int i = 0; i < 5; ++i) { float2 v = xp[i]; xv[2 * i] = v.x; xv[2 * i + 1] = v.y; }

        // ---- Layer 1: 10 -> 64 (16 pairs per thread) ----
        u64 acc1[16];
#pragma unroll
        for (int k = 0; k < 16; ++k) acc1[k] = 0ull;
#pragma unroll
        for (int i = 0; i < 10; ++i) {
            u64 h2 = pack2(xv[i], xv[i]);
#pragma unroll
            for (int k = 0; k < 16; ++k)
                acc1[k] = ffma2(h2, w1[i * 32 + k], acc1[k]);
        }
        unsigned msk1 = lif_update<16>(acc1, m1);
        unsigned oth1 = __shfl_xor_sync(0xffffffffu, msk1, 1);
        u64 f1 = half ? ((u64)oth1 | ((u64)msk1 << 32))
                      : ((u64)msk1 | ((u64)oth1 << 32));

        // ---- Layer 2: 64 -> 32 (8 pairs) ----
        u64 acc2[8];
        dot_mask<u64, 64, 8>(f1, w2, acc2);
        unsigned msk2 = lif_update<8>(acc2, m2);
        unsigned oth2 = __shfl_xor_sync(0xffffffffu, msk2, 1);
        unsigned f2 = half ? (oth2 | (msk2 << 16)) : (msk2 | (oth2 << 16));

        // ---- Layer 3: 32 -> 32 (8 pairs) ----
        u64 acc3[8];
        dot_mask<unsigned, 32, 8>(f2, w3, acc3);
        unsigned msk3 = lif_update<8>(acc3, m3);
        unsigned oth3 = __shfl_xor_sync(0xffffffffu, msk3, 1);
        unsigned f3 = half ? (oth3 | (msk3 << 16)) : (msk3 | (oth3 << 16));

        // ---- Layer 4: 32 -> 16 (4 pairs) ----
        u64 acc4[4];
        dot_mask<unsigned, 32, 4>(f3, w4, acc4);
        unsigned msk4 = lif_update<4>(acc4, m4);
        unsigned oth4 = __shfl_xor_sync(0xffffffffu, msk4, 1);
        unsigned f4 = half ? (oth4 | (msk4 << 8)) : (msk4 | (oth4 << 8));

        // ---- Layer 5: 16 -> 6 (padded to 8; 2 pairs) ----
        u64 acc5[2];
        dot_mask<unsigned, 16, 2>(f4, w5, acc5);
        float s[4];
#pragma unroll
        for (int k = 0; k < 2; ++k) {
            float a0, a1; unpack2(acc5[k], a0, a1);
            float mA = m5[2 * k], mB = m5[2 * k + 1];
            float rA = mA > THRESHF ? THRESHF : 0.0f;
            float rB = mB > THRESHF ? THRESHF : 0.0f;
            mA = fmaf(BETAF, mA, a0 - rA);
            mB = fmaf(BETAF, mB, a1 - rB);
            m5[2 * k] = mA; m5[2 * k + 1] = mB;
            s[2 * k]     = mA > THRESHF ? 1.0f : 0.0f;
            s[2 * k + 1] = mB > THRESHF ? 1.0f : 0.0f;
        }

        // ---- write out[t, e, 0:6]: half0 -> neurons 0..3, half1 -> 4..5 ----
        float* op = out + ((size_t)t * BATCH + (size_t)e) * 6;
        if (!half) {
            *(float2*)(op)     = make_float2(s[0], s[1]);
            *(float2*)(op + 2) = make_float2(s[2], s[3]);
        } else {
            *(float2*)(op + 4) = make_float2(s[0], s[1]);
        }
    }
}

extern "C" void kernel_launch(void* const* d_in, const int* in_sizes, int n_in,
                              void* d_out, int out_size) {
    // Identify inputs by element count (robust to metadata ordering).
    const float *x = nullptr, *W1 = nullptr, *W2 = nullptr, *W3 = nullptr,
                *W4 = nullptr, *W5 = nullptr;
    for (int i = 0; i < n_in; ++i) {
        const float* p = (const float*)d_in[i];
        switch (in_sizes[i]) {
            case 52428800: x  = p; break;  // (20, 262144, 10)
            case 640:      W1 = p; break;  // (64, 10)
            case 2048:     W2 = p; break;  // (32, 64)
            case 1024:     W3 = p; break;  // (32, 32)
            case 512:      W4 = p; break;  // (16, 32)
            case 96:       W5 = p; break;  // (6, 16)
            default: break;
        }
    }
    float* out = (float*)d_out;
    // 2 threads per batch element
    lif_kernel<<<(2 * BATCH) / 256, 256>>>(x, W1, W2, W3, W4, W5, out);
}